// round 1
// baseline (speedup 1.0000x reference)
#include <cuda_runtime.h>
#include <cstdint>
#include <cstddef>

#define TOKENS 1024
#define HIDDEN 2048
#define INTER  4096
#define NEXP   8

#define BM 64
#define BN 64
#define BK 32
#define PADK 36   // smem row stride (uint32) to stagger banks
#define NTH 128

// ---------------- device scratch (allocation-free) ----------------
__device__ int   g_count[NEXP];
__device__ int   g_tok[NEXP][TOKENS];
__device__ float g_w[NEXP][TOKENS];
// act scratch: [E][TOKENS][INTER] fp32 = 134 MB
__device__ float g_act[(size_t)NEXP * TOKENS * INTER];

// ---------------- helpers ----------------
__device__ __forceinline__ uint32_t f2tf32(float f) {
    uint32_t u;
    asm("cvt.rna.tf32.f32 %0, %1;" : "=r"(u) : "f"(f));
    return u;
}

__device__ __forceinline__ void mma_tf32(float c[4],
                                         uint32_t a0, uint32_t a1, uint32_t a2, uint32_t a3,
                                         uint32_t b0, uint32_t b1) {
    asm volatile(
        "mma.sync.aligned.m16n8k8.row.col.f32.tf32.tf32.f32 "
        "{%0,%1,%2,%3}, {%4,%5,%6,%7}, {%8,%9}, {%0,%1,%2,%3};\n"
        : "+f"(c[0]), "+f"(c[1]), "+f"(c[2]), "+f"(c[3])
        : "r"(a0), "r"(a1), "r"(a2), "r"(a3), "r"(b0), "r"(b1));
}

// ---------------- kernel 0: zero out + counts ----------------
__global__ void zero_kernel(float* __restrict__ out) {
    int i = blockIdx.x * blockDim.x + threadIdx.x;
    float4 z = make_float4(0.f, 0.f, 0.f, 0.f);
    reinterpret_cast<float4*>(out)[i] = z;   // grid sized to cover TOKENS*HIDDEN/4 exactly
    if (blockIdx.x == 0 && threadIdx.x < NEXP) g_count[threadIdx.x] = 0;
}

// ---------------- kernel 1: router (softmax -> top2 -> renorm -> scatter) ----------------
__global__ void router_kernel(const float* __restrict__ logits) {
    int t = blockIdx.x * blockDim.x + threadIdx.x;
    if (t >= TOKENS) return;
    float l[NEXP];
#pragma unroll
    for (int j = 0; j < NEXP; j++) l[j] = logits[t * NEXP + j];

    // top-2 (ties -> lowest index, matching lax.top_k)
    int i0 = 0;
#pragma unroll
    for (int j = 1; j < NEXP; j++) if (l[j] > l[i0]) i0 = j;
    int i1 = -1;
#pragma unroll
    for (int j = 0; j < NEXP; j++) {
        if (j == i0) continue;
        if (i1 < 0 || l[j] > l[i1]) i1 = j;
    }
    // renormalized top-2 softmax == softmax over the two logits
    float e1 = __expf(l[i1] - l[i0]);      // <= 1
    float w1 = e1 / (1.f + e1);
    float w0 = 1.f / (1.f + e1);

    int p0 = atomicAdd(&g_count[i0], 1);
    g_tok[i0][p0] = t;  g_w[i0][p0] = w0;
    int p1 = atomicAdd(&g_count[i1], 1);
    g_tok[i1][p1] = t;  g_w[i1][p1] = w1;
}

// ---------------- kernel 2: grouped GEMM1 (X @ W13^T) + SwiGLU -> g_act ----------------
// Block computes a [BM x BN] gate tile AND its paired up tile (row + INTER) sharing A.
__global__ void __launch_bounds__(NTH)
gemm1_kernel(const float* __restrict__ X, const float* __restrict__ W13) {
    const int e = blockIdx.z;
    const int ne = g_count[e];
    const int row0 = blockIdx.y * BM;
    if (row0 >= ne) return;
    const int col0 = blockIdx.x * BN;

    __shared__ uint32_t As[BM][PADK];
    __shared__ uint32_t Bg[BN][PADK];
    __shared__ uint32_t Bu[BN][PADK];

    const int tid  = threadIdx.x;
    const int warp = tid >> 5, lane = tid & 31;
    const int g  = lane >> 2, t4 = lane & 3;
    const int wm = (warp >> 1) * 32, wn = (warp & 1) * 32;

    const int lr = tid >> 3;          // 0..15
    const int lk = (tid & 7) * 4;     // 0..28 step 4

    // gather pointers for the 4 A-rows this thread loads
    const float* aptr[4];
#pragma unroll
    for (int it = 0; it < 4; it++) {
        int r = row0 + lr + it * 16;
        int tk = (r < ne) ? g_tok[e][r] : -1;
        aptr[it] = (tk >= 0) ? (X + (size_t)tk * HIDDEN) : nullptr;
    }
    const float* wbase = W13 + (size_t)e * 2 * INTER * HIDDEN;

    float accG[2][4][4];
    float accU[2][4][4];
#pragma unroll
    for (int mt = 0; mt < 2; mt++)
#pragma unroll
        for (int nt = 0; nt < 4; nt++)
#pragma unroll
            for (int i = 0; i < 4; i++) { accG[mt][nt][i] = 0.f; accU[mt][nt][i] = 0.f; }

    for (int k0 = 0; k0 < HIDDEN; k0 += BK) {
#pragma unroll
        for (int it = 0; it < 4; it++) {
            int m = lr + it * 16;
            float4 va = aptr[it] ? *reinterpret_cast<const float4*>(aptr[it] + k0 + lk)
                                 : make_float4(0.f, 0.f, 0.f, 0.f);
            As[m][lk + 0] = f2tf32(va.x); As[m][lk + 1] = f2tf32(va.y);
            As[m][lk + 2] = f2tf32(va.z); As[m][lk + 3] = f2tf32(va.w);

            const float4 vg = *reinterpret_cast<const float4*>(
                wbase + (size_t)(col0 + m) * HIDDEN + k0 + lk);
            Bg[m][lk + 0] = f2tf32(vg.x); Bg[m][lk + 1] = f2tf32(vg.y);
            Bg[m][lk + 2] = f2tf32(vg.z); Bg[m][lk + 3] = f2tf32(vg.w);

            const float4 vu = *reinterpret_cast<const float4*>(
                wbase + (size_t)(col0 + m + INTER) * HIDDEN + k0 + lk);
            Bu[m][lk + 0] = f2tf32(vu.x); Bu[m][lk + 1] = f2tf32(vu.y);
            Bu[m][lk + 2] = f2tf32(vu.z); Bu[m][lk + 3] = f2tf32(vu.w);
        }
        __syncthreads();

#pragma unroll
        for (int kk = 0; kk < 4; kk++) {
            const int kb = kk * 8;
            uint32_t a[2][4];
#pragma unroll
            for (int mt = 0; mt < 2; mt++) {
                int ar = wm + mt * 16;
                a[mt][0] = As[ar + g    ][kb + t4];
                a[mt][1] = As[ar + g + 8][kb + t4];
                a[mt][2] = As[ar + g    ][kb + t4 + 4];
                a[mt][3] = As[ar + g + 8][kb + t4 + 4];
            }
#pragma unroll
            for (int nt = 0; nt < 4; nt++) {
                int bc = wn + nt * 8 + g;
                uint32_t bg0 = Bg[bc][kb + t4], bg1 = Bg[bc][kb + t4 + 4];
                uint32_t bu0 = Bu[bc][kb + t4], bu1 = Bu[bc][kb + t4 + 4];
#pragma unroll
                for (int mt = 0; mt < 2; mt++) {
                    mma_tf32(accG[mt][nt], a[mt][0], a[mt][1], a[mt][2], a[mt][3], bg0, bg1);
                    mma_tf32(accU[mt][nt], a[mt][0], a[mt][1], a[mt][2], a[mt][3], bu0, bu1);
                }
            }
        }
        __syncthreads();
    }

    // epilogue: act = silu(gate) * up
    float* actbase = g_act + (size_t)e * TOKENS * INTER;
#pragma unroll
    for (int mt = 0; mt < 2; mt++) {
        int r_lo = row0 + wm + mt * 16 + g;
        int r_hi = r_lo + 8;
#pragma unroll
        for (int nt = 0; nt < 4; nt++) {
            int c = col0 + wn + nt * 8 + 2 * t4;
            if (r_lo < ne) {
                float g0 = accG[mt][nt][0], g1 = accG[mt][nt][1];
                float a0 = g0 / (1.f + __expf(-g0)) * accU[mt][nt][0];
                float a1 = g1 / (1.f + __expf(-g1)) * accU[mt][nt][1];
                *reinterpret_cast<float2*>(actbase + (size_t)r_lo * INTER + c) = make_float2(a0, a1);
            }
            if (r_hi < ne) {
                float g2 = accG[mt][nt][2], g3 = accG[mt][nt][3];
                float a2 = g2 / (1.f + __expf(-g2)) * accU[mt][nt][2];
                float a3 = g3 / (1.f + __expf(-g3)) * accU[mt][nt][3];
                *reinterpret_cast<float2*>(actbase + (size_t)r_hi * INTER + c) = make_float2(a2, a3);
            }
        }
    }
}

// ---------------- kernel 3: grouped GEMM2 (act @ W2^T) -> weighted scatter ----------------
__global__ void __launch_bounds__(NTH)
gemm2_kernel(const float* __restrict__ W2, float* __restrict__ out) {
    const int e = blockIdx.z;
    const int ne = g_count[e];
    const int row0 = blockIdx.y * BM;
    if (row0 >= ne) return;
    const int col0 = blockIdx.x * BN;

    __shared__ uint32_t As[BM][PADK];
    __shared__ uint32_t Bs[BN][PADK];

    const int tid  = threadIdx.x;
    const int warp = tid >> 5, lane = tid & 31;
    const int g  = lane >> 2, t4 = lane & 3;
    const int wm = (warp >> 1) * 32, wn = (warp & 1) * 32;

    const int lr = tid >> 3;
    const int lk = (tid & 7) * 4;

    const float* abase = g_act + (size_t)e * TOKENS * INTER;
    const float* bbase = W2 + (size_t)e * HIDDEN * INTER;

    bool avalid[4];
#pragma unroll
    for (int it = 0; it < 4; it++) avalid[it] = (row0 + lr + it * 16) < ne;

    float acc[2][4][4];
#pragma unroll
    for (int mt = 0; mt < 2; mt++)
#pragma unroll
        for (int nt = 0; nt < 4; nt++)
#pragma unroll
            for (int i = 0; i < 4; i++) acc[mt][nt][i] = 0.f;

    for (int k0 = 0; k0 < INTER; k0 += BK) {
#pragma unroll
        for (int it = 0; it < 4; it++) {
            int m = lr + it * 16;
            float4 va = avalid[it]
                ? *reinterpret_cast<const float4*>(abase + (size_t)(row0 + m) * INTER + k0 + lk)
                : make_float4(0.f, 0.f, 0.f, 0.f);
            As[m][lk + 0] = f2tf32(va.x); As[m][lk + 1] = f2tf32(va.y);
            As[m][lk + 2] = f2tf32(va.z); As[m][lk + 3] = f2tf32(va.w);

            const float4 vb = *reinterpret_cast<const float4*>(
                bbase + (size_t)(col0 + m) * INTER + k0 + lk);
            Bs[m][lk + 0] = f2tf32(vb.x); Bs[m][lk + 1] = f2tf32(vb.y);
            Bs[m][lk + 2] = f2tf32(vb.z); Bs[m][lk + 3] = f2tf32(vb.w);
        }
        __syncthreads();

#pragma unroll
        for (int kk = 0; kk < 4; kk++) {
            const int kb = kk * 8;
            uint32_t a[2][4];
#pragma unroll
            for (int mt = 0; mt < 2; mt++) {
                int ar = wm + mt * 16;
                a[mt][0] = As[ar + g    ][kb + t4];
                a[mt][1] = As[ar + g + 8][kb + t4];
                a[mt][2] = As[ar + g    ][kb + t4 + 4];
                a[mt][3] = As[ar + g + 8][kb + t4 + 4];
            }
#pragma unroll
            for (int nt = 0; nt < 4; nt++) {
                int bc = wn + nt * 8 + g;
                uint32_t b0 = Bs[bc][kb + t4], b1 = Bs[bc][kb + t4 + 4];
#pragma unroll
                for (int mt = 0; mt < 2; mt++)
                    mma_tf32(acc[mt][nt], a[mt][0], a[mt][1], a[mt][2], a[mt][3], b0, b1);
            }
        }
        __syncthreads();
    }

    // epilogue: out[token, col] += w * acc   (2 commutative fp32 adds per element)
#pragma unroll
    for (int mt = 0; mt < 2; mt++) {
        int r_lo = row0 + wm + mt * 16 + g;
        int r_hi = r_lo + 8;
        int   tok_lo = 0, tok_hi = 0;
        float w_lo = 0.f, w_hi = 0.f;
        if (r_lo < ne) { tok_lo = g_tok[e][r_lo]; w_lo = g_w[e][r_lo]; }
        if (r_hi < ne) { tok_hi = g_tok[e][r_hi]; w_hi = g_w[e][r_hi]; }
#pragma unroll
        for (int nt = 0; nt < 4; nt++) {
            int c = col0 + wn + nt * 8 + 2 * t4;
            if (r_lo < ne) {
                atomicAdd(&out[(size_t)tok_lo * HIDDEN + c    ], w_lo * acc[mt][nt][0]);
                atomicAdd(&out[(size_t)tok_lo * HIDDEN + c + 1], w_lo * acc[mt][nt][1]);
            }
            if (r_hi < ne) {
                atomicAdd(&out[(size_t)tok_hi * HIDDEN + c    ], w_hi * acc[mt][nt][2]);
                atomicAdd(&out[(size_t)tok_hi * HIDDEN + c + 1], w_hi * acc[mt][nt][3]);
            }
        }
    }
}

// ---------------- launch ----------------
extern "C" void kernel_launch(void* const* d_in, const int* in_sizes, int n_in,
                              void* d_out, int out_size) {
    const float* X      = (const float*)d_in[0];
    const float* logits = (const float*)d_in[1];
    const float* W13    = (const float*)d_in[2];
    const float* W2     = (const float*)d_in[3];
    float* out = (float*)d_out;

    zero_kernel<<<(TOKENS * HIDDEN / 4) / 256, 256>>>(out);
    router_kernel<<<(TOKENS + 255) / 256, 256>>>(logits);

    dim3 g1(INTER / BN, TOKENS / BM, NEXP);
    gemm1_kernel<<<g1, NTH>>>(X, W13);

    dim3 g2(HIDDEN / BN, TOKENS / BM, NEXP);
    gemm2_kernel<<<g2, NTH>>>(W2, out);
}